// round 4
// baseline (speedup 1.0000x reference)
#include <cuda_runtime.h>
#include <cstdint>

#define FULLMASK 0xFFFFFFFFu
#define AR_P    48
#define TLEN    168          // forecast length
#define TQ      42           // TLEN/4
#define HIST    336
#define LV_BLOCKS 128
#define TPB     256

// Precomputed coefficient matrix, transposed: g_WT[j*TLEN + t] = W[t][j]
__device__ float g_WT[AR_P * TLEN];
__device__ float g_c[TLEN];

// ---------------------------------------------------------------------------
// Kernel 1: one warp builds W and c via the companion rank-1 shift recursion:
//   W[0] = phi;  W[t][j] = W[t-1][j-1] + W[t-1][47]*phi[j]
//   c[t] = bias * (1 + sum_{u<t} W[u][47])
// Lanes 0..31 hold column j=l in va; lanes 0..15 additionally hold j=l+32 in vb.
// ---------------------------------------------------------------------------
__global__ void build_w_kernel(const float* __restrict__ phi,
                               const float* __restrict__ bias) {
    const int l = threadIdx.x;
    const float pa = phi[l];
    const float pb = (l < 16) ? phi[l + 32] : 0.0f;
    float va = pa;
    float vb = pb;
    const float b0 = bias[0];
    float acc = 1.0f;

    for (int t = 0; t < TLEN; ++t) {
        // store row t (W[t][j] at g_WT[j*TLEN + t])
        g_WT[l * TLEN + t] = va;
        if (l < 16) g_WT[(l + 32) * TLEN + t] = vb;
        if (l == 0) g_c[t] = b0 * acc;

        const float v47 = __shfl_sync(FULLMASK, vb, 15);   // W[t][47]
        acc += v47;

        float sa = __shfl_up_sync(FULLMASK, va, 1);        // shift: v[l-1]
        const float a31 = __shfl_sync(FULLMASK, va, 31);   // v[31]
        float sb = __shfl_up_sync(FULLMASK, vb, 1);        // v[l+31]
        if (l == 0) { sa = 0.0f; sb = a31; }

        va = fmaf(v47, pa, sa);
        vb = fmaf(v47, pb, sb);
    }
}

// ---------------------------------------------------------------------------
// Packed fp32x2 helpers (Blackwell fma.rn.f32x2: 2x FFMA throughput)
// ---------------------------------------------------------------------------
__device__ __forceinline__ unsigned long long pk2(float x, float y) {
    unsigned long long r;
    asm("mov.b64 %0, {%1, %2};" : "=l"(r) : "f"(x), "f"(y));
    return r;
}
__device__ __forceinline__ unsigned long long fma2(unsigned long long a,
                                                   unsigned long long b,
                                                   unsigned long long c) {
    unsigned long long d;
    asm("fma.rn.f32x2 %0, %1, %2, %3;" : "=l"(d) : "l"(a), "l"(b), "l"(c));
    return d;
}
__device__ __forceinline__ float2 up2(unsigned long long v) {
    float2 f;
    asm("mov.b64 {%0, %1}, %2;" : "=f"(f.x), "=f"(f.y) : "l"(v));
    return f;
}

// ---------------------------------------------------------------------------
// Kernel 2: fused main kernel.
//   blocks [0, LV_BLOCKS)          : coalesced grid-stride fill of logvar half
//   blocks [LV_BLOCKS, LV+B/TPB)   : one series per thread, GEMV with f32x2
// LV blocks come first so their DRAM stores overlap mu-blocks' FMA work.
// ---------------------------------------------------------------------------
__global__ void __launch_bounds__(TPB)
forecast_kernel(const float* __restrict__ enc_l,
                const float* __restrict__ mu_p,
                const float* __restrict__ sigma_p,
                const float* __restrict__ ls2_p,
                float* __restrict__ out,
                int B) {
    if (blockIdx.x < LV_BLOCKS) {
        // logvar = log_sigma2 + 2*log(sigma), broadcast over (B, TLEN)
        const float L = ls2_p[0] + 2.0f * logf(sigma_p[0]);
        float4 v; v.x = L; v.y = L; v.z = L; v.w = L;
        float4* dst = reinterpret_cast<float4*>(out + (size_t)B * TLEN);
        const int n4 = (B * TLEN) >> 2;
        for (int i = blockIdx.x * TPB + threadIdx.x; i < n4; i += LV_BLOCKS * TPB)
            dst[i] = v;
        return;
    }

    __shared__ float sW[AR_P * TLEN];   // 31.5 KB, WT layout
    __shared__ float sc[TLEN];

    const int tid = threadIdx.x;
    // cooperative load of W (coalesced float4) and c
    {
        const float4* src4 = reinterpret_cast<const float4*>(g_WT);
        float4* dst4 = reinterpret_cast<float4*>(sW);
        for (int i = tid; i < (AR_P * TLEN) / 4; i += TPB) dst4[i] = src4[i];
        for (int i = tid; i < TLEN; i += TPB) sc[i] = g_c[i];
    }

    const float mu = mu_p[0];
    const float sigma = sigma_p[0];
    const float inv = 1.0f / sigma;
    __syncthreads();

    const int b = (blockIdx.x - LV_BLOCKS) * TPB + tid;
    if (b >= B) return;

    // Load + standardize last 48 history values; duplicate into f32x2 pairs.
    unsigned long long s2[AR_P];
    {
        const float4* src = reinterpret_cast<const float4*>(
            enc_l + (size_t)b * HIST + (HIST - AR_P));
#pragma unroll
        for (int q = 0; q < AR_P / 4; ++q) {
            const float4 y = src[q];
            const float a0 = (y.x - mu) * inv;
            const float a1 = (y.y - mu) * inv;
            const float a2 = (y.z - mu) * inv;
            const float a3 = (y.w - mu) * inv;
            s2[4 * q + 0] = pk2(a0, a0);
            s2[4 * q + 1] = pk2(a1, a1);
            s2[4 * q + 2] = pk2(a2, a2);
            s2[4 * q + 3] = pk2(a3, a3);
        }
    }

    const unsigned long long sg2 = pk2(sigma, sigma);
    const unsigned long long mu2 = pk2(mu, mu);
    float* orow = out + (size_t)b * TLEN;

#pragma unroll 2
    for (int tq = 0; tq < TQ; ++tq) {
        const float4 c4 = *reinterpret_cast<const float4*>(sc + 4 * tq);
        unsigned long long a0 = pk2(c4.x, c4.y);   // accumulators for t=4tq..4tq+3
        unsigned long long a1 = pk2(c4.z, c4.w);

#pragma unroll
        for (int j = 0; j < AR_P; ++j) {
            // broadcast LDS.128: (W[j][4tq..4tq+3]) — all threads same address
            const ulonglong2 w = *reinterpret_cast<const ulonglong2*>(
                sW + j * TLEN + 4 * tq);
            a0 = fma2(w.x, s2[j], a0);
            a1 = fma2(w.y, s2[j], a1);
        }

        // de-standardize: out = pred*sigma + mu
        const unsigned long long r0 = fma2(a0, sg2, mu2);
        const unsigned long long r1 = fma2(a1, sg2, mu2);
        const float2 f0 = up2(r0);
        const float2 f1 = up2(r1);
        float4 o; o.x = f0.x; o.y = f0.y; o.z = f1.x; o.w = f1.y;
        *reinterpret_cast<float4*>(orow + 4 * tq) = o;
    }
}

// ---------------------------------------------------------------------------
extern "C" void kernel_launch(void* const* d_in, const int* in_sizes, int n_in,
                              void* d_out, int out_size) {
    // inputs: enc_l, enc_t, enc_w, enc_s, phi, bias, log_sigma2, mu, sigma
    const float* enc_l = (const float*)d_in[0];
    const float* phi   = (const float*)d_in[4];
    const float* bias  = (const float*)d_in[5];
    const float* ls2   = (const float*)d_in[6];
    const float* mu    = (const float*)d_in[7];
    const float* sigma = (const float*)d_in[8];
    float* out = (float*)d_out;

    const int B = in_sizes[0] / HIST;   // enc_l is (B, HIST, 1)

    build_w_kernel<<<1, 32>>>(phi, bias);

    const int mu_blocks = (B + TPB - 1) / TPB;
    forecast_kernel<<<LV_BLOCKS + mu_blocks, TPB>>>(enc_l, mu, sigma, ls2, out, B);
}